// round 15
// baseline (speedup 1.0000x reference)
#include <cuda_runtime.h>
#include <cuda_bf16.h>
#include <cstdint>

// GarNetLayer: out[b,s,n] = sw[b,s] * (sum_v w[b,v,s]*fi[b,v,n]) / V^2,
//   w = exp(-d_av^2), sw = sum_v w.   B=4096, V=128, S=16, N=64.
//
// One warp per batch. Thread -> (n-quad nq=lane&15, s-half sh=lane>>4).
// fi streamed from GMEM via __ldcs (LDG.128 evict-first, read exactly once;
// 1-deep 4-iter software pipeline -> MLP~8 per warp). w staged in smem
// (8KB/batch), fetched as 2x LDS.128 per v. Accumulators are f32x2 pairs
// over adjacent s (FFMA2). Output via __stcs (streaming store).

#define GN_V 128
#define GN_S 16
#define GN_N 64
#define GN_WARPS 4          // batches per block
#define GN_T (GN_WARPS * 32)

#define FMA2(acc, a, b) \
    asm("fma.rn.f32x2 %0, %1, %2, %0;" : "+l"(acc) : "l"(a), "l"(b))
#define PACK2(dst, lo, hi) \
    asm("mov.b64 %0, {%1,%2};" : "=l"(dst) : "f"(lo), "f"(hi))
#define UNPACK2(lo, hi, src) \
    asm("mov.b64 {%0,%1}, %2;" : "=f"(lo), "=f"(hi) : "l"(src))

__global__ __launch_bounds__(GN_T)
void garnet_kernel(const float* __restrict__ fi,   // [B, V, N]
                   const float* __restrict__ dav,  // [B, V, S]
                   float* __restrict__ out,        // [B, S*N]
                   int B)
{
    __shared__ float s_w[GN_WARPS][GN_V * GN_S];   // 32 KB
    __shared__ float s_sw[GN_WARPS][GN_S];

    const int wid  = threadIdx.x >> 5;
    const int lane = threadIdx.x & 31;
    const int b    = blockIdx.x * GN_WARPS + wid;
    if (b >= B) return;                 // whole warp exits together

    float* wbuf = s_w[wid];

    // ---- stage w = exp(-d^2): 512 float4, 16 per lane, coalesced ----
    const float4* d4 = (const float4*)(dav + (size_t)b * (GN_V * GN_S));
    float4* w4 = (float4*)wbuf;
    #pragma unroll
    for (int i = 0; i < (GN_V * GN_S / 4) / 32; i++) {
        float4 dv = __ldcs(&d4[lane + i * 32]);        // streaming read
        float4 wv;
        wv.x = __expf(-dv.x * dv.x);
        wv.y = __expf(-dv.y * dv.y);
        wv.z = __expf(-dv.z * dv.z);
        wv.w = __expf(-dv.w * dv.w);
        w4[lane + i * 32] = wv;
    }
    __syncwarp();

    // ---- sw[s] = (1/V^2) * sum_v w[v][s]  (16 lanes, conflict-free stride-16) ----
    if (lane < GN_S) {
        float acc = 0.f;
        #pragma unroll 16
        for (int v = 0; v < GN_V; v++) acc += wbuf[v * GN_S + lane];
        s_sw[wid][lane] = acc * (1.0f / ((float)GN_V * (float)GN_V));
    }
    __syncwarp();

    // ---- main loop: stream fi, accumulate 8 s x 4 n per thread ----
    const int nq = lane & 15;   // n-quad: n = nq*4..nq*4+3
    const int sh = lane >> 4;   // s-half: s = sh*8..sh*8+7
    const float4* fip = (const float4*)(fi + (size_t)b * (GN_V * GN_N)) + nq;
    const float4* wp4 = (const float4*)(wbuf + sh * 8);   // 16B-aligned

    unsigned long long acc[4][4];   // acc[sp][n]: (s=sh*8+2sp, s+1) x column n
    #pragma unroll
    for (int sp = 0; sp < 4; sp++)
        #pragma unroll
        for (int n = 0; n < 4; n++) acc[sp][n] = 0ull;

    // software pipeline: group of 4 v-iters prefetched one group ahead
    float4 fbuf[4];
    #pragma unroll
    for (int j = 0; j < 4; j++)
        fbuf[j] = __ldcs(&fip[j * (GN_N / 4)]);         // v = 0..3

    for (int vb = 0; vb < GN_V; vb += 4) {
        float4 fcur[4];
        #pragma unroll
        for (int j = 0; j < 4; j++) fcur[j] = fbuf[j];

        if (vb + 4 < GN_V) {
            #pragma unroll
            for (int j = 0; j < 4; j++)
                fbuf[j] = __ldcs(&fip[(vb + 4 + j) * (GN_N / 4)]);  // prefetch
        }

        #pragma unroll
        for (int j = 0; j < 4; j++) {
            const int v = vb + j;
            float4 f = fcur[j];

            float4 wa = wp4[v * (GN_S / 4)];            // s = sh*8 + 0..3
            float4 wb = wp4[v * (GN_S / 4) + 1];        // s = sh*8 + 4..7

            unsigned long long wpr[4];
            PACK2(wpr[0], wa.x, wa.y);
            PACK2(wpr[1], wa.z, wa.w);
            PACK2(wpr[2], wb.x, wb.y);
            PACK2(wpr[3], wb.z, wb.w);

            unsigned long long fd[4];
            PACK2(fd[0], f.x, f.x);
            PACK2(fd[1], f.y, f.y);
            PACK2(fd[2], f.z, f.z);
            PACK2(fd[3], f.w, f.w);

            #pragma unroll
            for (int sp = 0; sp < 4; sp++) {
                FMA2(acc[sp][0], wpr[sp], fd[0]);
                FMA2(acc[sp][1], wpr[sp], fd[1]);
                FMA2(acc[sp][2], wpr[sp], fd[2]);
                FMA2(acc[sp][3], wpr[sp], fd[3]);
            }
        }
    }

    // ---- epilogue: scale by sw[s], streaming-store float4 per s ----
    float* ob = out + (size_t)b * (GN_S * GN_N) + nq * 4;
    #pragma unroll
    for (int sp = 0; sp < 4; sp++) {
        float lo0, hi0, lo1, hi1, lo2, hi2, lo3, hi3;
        UNPACK2(lo0, hi0, acc[sp][0]);
        UNPACK2(lo1, hi1, acc[sp][1]);
        UNPACK2(lo2, hi2, acc[sp][2]);
        UNPACK2(lo3, hi3, acc[sp][3]);
        const int s0 = sh * 8 + sp * 2;
        float sw0 = s_sw[wid][s0];
        float sw1 = s_sw[wid][s0 + 1];
        float4 r0 = make_float4(lo0 * sw0, lo1 * sw0, lo2 * sw0, lo3 * sw0);
        float4 r1 = make_float4(hi0 * sw1, hi1 * sw1, hi2 * sw1, hi3 * sw1);
        __stcs((float4*)(ob + (size_t)s0 * GN_N),       r0);
        __stcs((float4*)(ob + (size_t)(s0 + 1) * GN_N), r1);
    }
}

extern "C" void kernel_launch(void* const* d_in, const int* in_sizes, int n_in,
                              void* d_out, int out_size)
{
    const float* fi  = (const float*)d_in[0];   // [B, V, N]
    const float* dav = (const float*)d_in[1];   // [B, V, S]
    float* out = (float*)d_out;                 // [B, S*N] float32

    const int B = in_sizes[0] / (GN_V * GN_N);  // 4096 for reference shapes
    const int grid = (B + GN_WARPS - 1) / GN_WARPS;

    garnet_kernel<<<grid, GN_T>>>(fi, dav, out, B);
}

// round 16
// speedup vs baseline: 1.0065x; 1.0065x over previous
#include <cuda_runtime.h>
#include <cuda_bf16.h>
#include <cstdint>

// GarNetLayer: out[b,s,n] = sw[b,s] * (sum_v w[b,v,s]*fi[b,v,n]) / V^2,
//   w = exp(-d_av^2), sw = sum_v w.   B=4096, V=128, S=16, N=64.
//
// R15 post-mortem: 49.7us, DRAM 44.9%, occ 23.5% (regs=88) -> latency-bound.
// Fix: 2 warps/batch, 16 outputs/thread (4s x 4n), acc paired over n so the
// fi float4 provides f32x2 multiplier pairs for free. Rolling 4-deep fbuf.
// __launch_bounds__(128,8) -> <=64 regs -> 8 blocks/SM (50% occ).

#define GN_V 128
#define GN_S 16
#define GN_N 64
#define GN_BT 64                 // threads per batch (2 warps)
#define GN_BB 2                  // batches per block
#define GN_T (GN_BT * GN_BB)     // 128

#define FMA2(acc, a, b) \
    asm("fma.rn.f32x2 %0, %1, %2, %0;" : "+l"(acc) : "l"(a), "l"(b))
#define PACK2(dst, lo, hi) \
    asm("mov.b64 %0, {%1,%2};" : "=l"(dst) : "f"(lo), "f"(hi))
#define UNPACK2(lo, hi, src) \
    asm("mov.b64 {%0,%1}, %2;" : "=f"(lo), "=f"(hi) : "l"(src))

__global__ __launch_bounds__(GN_T, 8)
void garnet_kernel(const float* __restrict__ fi,   // [B, V, N]
                   const float* __restrict__ dav,  // [B, V, S]
                   float* __restrict__ out,        // [B, S*N]
                   int B)
{
    __shared__ float s_w[GN_BB][GN_V * GN_S];   // 16 KB
    __shared__ float s_sw[GN_BB][GN_S];

    const int tid = threadIdx.x;
    const int bb  = tid >> 6;            // batch within block
    const int t   = tid & (GN_BT - 1);   // 0..63 within batch
    const int b   = blockIdx.x * GN_BB + bb;
    if (b >= B) return;                  // sm_70+: syncthreads counts only non-exited

    float* wbuf = s_w[bb];

    // ---- stage w = exp(-d^2): 512 float4 per batch, 8 per thread, coalesced ----
    const float4* d4 = (const float4*)(dav + (size_t)b * (GN_V * GN_S));
    float4* w4 = (float4*)wbuf;
    #pragma unroll
    for (int k = 0; k < (GN_V * GN_S / 4) / GN_BT; k++) {
        float4 dv = __ldcs(&d4[t + k * GN_BT]);
        float4 wv;
        wv.x = __expf(-dv.x * dv.x);
        wv.y = __expf(-dv.y * dv.y);
        wv.z = __expf(-dv.z * dv.z);
        wv.w = __expf(-dv.w * dv.w);
        w4[t + k * GN_BT] = wv;
    }
    __syncthreads();

    // ---- sw[s] = (1/V^2) * sum_v w[v][s]  (16 threads, stride-16 banks) ----
    if (t < GN_S) {
        float acc = 0.f;
        #pragma unroll 16
        for (int v = 0; v < GN_V; v++) acc += wbuf[v * GN_S + t];
        s_sw[bb][t] = acc * (1.0f / ((float)GN_V * (float)GN_V));
    }
    __syncthreads();

    // ---- main loop: thread -> (nq = t&15, sq = t>>4); 4 s x 4 n outputs ----
    const int nq = t & 15;    // n = nq*4 .. nq*4+3
    const int sq = t >> 4;    // s = sq*4 .. sq*4+3
    const float4* fip = (const float4*)(fi + (size_t)b * (GN_V * GN_N)) + nq;
    const float4* wp4 = (const float4*)(wbuf + sq * 4);   // w[v][sq*4..+3]

    // acc[s][np]: f32x2 over (n = nq*4+2np, n+1), s local 0..3
    unsigned long long acc[4][2];
    #pragma unroll
    for (int s = 0; s < 4; s++) { acc[s][0] = 0ull; acc[s][1] = 0ull; }

    // rolling 4-deep prefetch: consume fbuf[j], immediately reload with v+4
    float4 fbuf[4];
    #pragma unroll
    for (int j = 0; j < 4; j++)
        fbuf[j] = __ldcs(&fip[j * (GN_N / 4)]);

    for (int vb = 0; vb < GN_V; vb += 4) {
        #pragma unroll
        for (int j = 0; j < 4; j++) {
            const int v = vb + j;
            float4 f = fbuf[j];
            if (vb + 4 < GN_V)
                fbuf[j] = __ldcs(&fip[(v + 4) * (GN_N / 4)]);

            float4 w = wp4[v * (GN_S / 4)];     // LDS.128, broadcast-2 per warp

            unsigned long long fd0, fd1;
            PACK2(fd0, f.x, f.y);               // natural pairs from LDG.128
            PACK2(fd1, f.z, f.w);

            unsigned long long wd;
            PACK2(wd, w.x, w.x);
            FMA2(acc[0][0], wd, fd0); FMA2(acc[0][1], wd, fd1);
            PACK2(wd, w.y, w.y);
            FMA2(acc[1][0], wd, fd0); FMA2(acc[1][1], wd, fd1);
            PACK2(wd, w.z, w.z);
            FMA2(acc[2][0], wd, fd0); FMA2(acc[2][1], wd, fd1);
            PACK2(wd, w.w, w.w);
            FMA2(acc[3][0], wd, fd0); FMA2(acc[3][1], wd, fd1);
        }
    }

    // ---- epilogue: scale by sw[s], streaming float4 store per s ----
    float* ob = out + (size_t)b * (GN_S * GN_N) + nq * 4;
    #pragma unroll
    for (int s = 0; s < 4; s++) {
        const int sg = sq * 4 + s;
        float sw = s_sw[bb][sg];
        float a0, a1, a2, a3;
        UNPACK2(a0, a1, acc[s][0]);
        UNPACK2(a2, a3, acc[s][1]);
        float4 r = make_float4(a0 * sw, a1 * sw, a2 * sw, a3 * sw);
        __stcs((float4*)(ob + (size_t)sg * GN_N), r);
    }
}

extern "C" void kernel_launch(void* const* d_in, const int* in_sizes, int n_in,
                              void* d_out, int out_size)
{
    const float* fi  = (const float*)d_in[0];   // [B, V, N]
    const float* dav = (const float*)d_in[1];   // [B, V, S]
    float* out = (float*)d_out;                 // [B, S*N] float32

    const int B = in_sizes[0] / (GN_V * GN_N);  // 4096 for reference shapes
    const int grid = (B + GN_BB - 1) / GN_BB;

    garnet_kernel<<<grid, GN_T>>>(fi, dav, out, B);
}